// round 1
// baseline (speedup 1.0000x reference)
#include <cuda_runtime.h>

// SubsurfaceFlowTerm: 3 tiny MLPs (4->6->6->1, tanh) -> sigmoid-affine params
// (S1max, ks, n) -> clip(ks*(S1/S1max)^n, 0, S1max).  N = 2,000,000 rows.
//
// Strategy: FMA-bound elementwise kernel. Weights (237 floats) in shared
// memory; each thread processes R=4 rows so every broadcast LDS of a weight
// feeds 4 FFMAs. All transcendentals via MUFU approx instructions.

#define RPT 4            // rows per thread
#define TPB 256          // threads per block

__device__ __forceinline__ float tanh_fast(float x) {
    float y;
    asm("tanh.approx.f32 %0, %1;" : "=f"(y) : "f"(x));
    return y;
}

__device__ __forceinline__ float rcp_fast(float x) {
    float y;
    asm("rcp.approx.f32 %0, %1;" : "=f"(y) : "f"(x));
    return y;
}

__device__ __forceinline__ float sigmoid_fast(float x) {
    // 1 / (1 + exp(-x))
    return rcp_fast(1.0f + __expf(-x));
}

__global__ void __launch_bounds__(TPB)
subsurface_flow_kernel(const float4* __restrict__ x4,   // [N] of float4 (row of 4)
                       const float*  __restrict__ S1,   // [N]
                       const float*  __restrict__ W1,   // [3,4,6]
                       const float*  __restrict__ b1,   // [3,6]
                       const float*  __restrict__ W2,   // [3,6,6]
                       const float*  __restrict__ b2,   // [3,6]
                       const float*  __restrict__ W3,   // [3,6,1]
                       const float*  __restrict__ b3,   // [3,1]
                       float* __restrict__ out,         // [N]
                       int n, int gstride)
{
    __shared__ float sW1[72];   // k*24 + d*6 + w
    __shared__ float sb1[18];   // k*6 + w
    __shared__ float sW2[108];  // k*36 + w*6 + v
    __shared__ float sb2[18];   // k*6 + v
    __shared__ float sW3[18];   // k*6 + v
    __shared__ float sb3[3];    // k

    const int tid = threadIdx.x;
    if (tid < 72)  sW1[tid] = W1[tid];
    if (tid < 18)  sb1[tid] = b1[tid];
    if (tid < 108) sW2[tid] = W2[tid];
    if (tid >= 128 && tid < 146) sb2[tid - 128] = b2[tid - 128];
    if (tid >= 160 && tid < 178) sW3[tid - 160] = W3[tid - 160];
    if (tid >= 192 && tid < 195) sb3[tid - 192] = b3[tid - 192];
    __syncthreads();

    const int t = blockIdx.x * TPB + tid;

    // Load R rows (coalesced: consecutive lanes -> consecutive rows)
    float xv[RPT][4];
    float s1v[RPT];
    int   row[RPT];
    bool  valid[RPT];
#pragma unroll
    for (int j = 0; j < RPT; ++j) {
        row[j]   = t + j * gstride;
        valid[j] = (row[j] < n);
        if (valid[j]) {
            float4 v = x4[row[j]];
            xv[j][0] = v.x; xv[j][1] = v.y; xv[j][2] = v.z; xv[j][3] = v.w;
            s1v[j]   = S1[row[j]];
        } else {
            xv[j][0] = xv[j][1] = xv[j][2] = xv[j][3] = 0.0f;
            s1v[j]   = 0.0f;
        }
    }

    // HydroParam bounds: lows [100, 0.01, 0.01], highs [500, 100, 10]
    const float lowk[3]   = {100.0f, 0.01f, 0.01f};
    const float rangek[3] = {400.0f, 99.99f, 9.99f};

    float vals[RPT][3];

#pragma unroll
    for (int k = 0; k < 3; ++k) {
        // ---- layer 1: 4 -> 6, tanh ----
        float h1[RPT][6];
#pragma unroll
        for (int w = 0; w < 6; ++w) {
            const float b = sb1[k * 6 + w];
#pragma unroll
            for (int j = 0; j < RPT; ++j) h1[j][w] = b;
        }
#pragma unroll
        for (int d = 0; d < 4; ++d) {
#pragma unroll
            for (int w = 0; w < 6; ++w) {
                const float wt = sW1[k * 24 + d * 6 + w];
#pragma unroll
                for (int j = 0; j < RPT; ++j)
                    h1[j][w] = fmaf(xv[j][d], wt, h1[j][w]);
            }
        }
#pragma unroll
        for (int j = 0; j < RPT; ++j)
#pragma unroll
            for (int w = 0; w < 6; ++w) h1[j][w] = tanh_fast(h1[j][w]);

        // ---- layer 2: 6 -> 6, tanh ----
        float h2[RPT][6];
#pragma unroll
        for (int v = 0; v < 6; ++v) {
            const float b = sb2[k * 6 + v];
#pragma unroll
            for (int j = 0; j < RPT; ++j) h2[j][v] = b;
        }
#pragma unroll
        for (int w = 0; w < 6; ++w) {
#pragma unroll
            for (int v = 0; v < 6; ++v) {
                const float wt = sW2[k * 36 + w * 6 + v];
#pragma unroll
                for (int j = 0; j < RPT; ++j)
                    h2[j][v] = fmaf(h1[j][w], wt, h2[j][v]);
            }
        }
#pragma unroll
        for (int j = 0; j < RPT; ++j)
#pragma unroll
            for (int v = 0; v < 6; ++v) h2[j][v] = tanh_fast(h2[j][v]);

        // ---- layer 3: 6 -> 1, sigmoid-affine ----
        float y[RPT];
        const float b3k = sb3[k];
#pragma unroll
        for (int j = 0; j < RPT; ++j) y[j] = b3k;
#pragma unroll
        for (int v = 0; v < 6; ++v) {
            const float wt = sW3[k * 6 + v];
#pragma unroll
            for (int j = 0; j < RPT; ++j)
                y[j] = fmaf(h2[j][v], wt, y[j]);
        }
#pragma unroll
        for (int j = 0; j < RPT; ++j)
            vals[j][k] = fmaf(rangek[k], sigmoid_fast(y[j]), lowk[k]);
    }

    // ---- hydrology term + clip ----
#pragma unroll
    for (int j = 0; j < RPT; ++j) {
        if (valid[j]) {
            const float S1max = vals[j][0];
            const float ksv   = vals[j][1];
            const float nv    = vals[j][2];
            const float ratio = s1v[j] * rcp_fast(S1max);
            float flow = ksv * __powf(ratio, nv);
            flow = fminf(flow, S1max);
            flow = fmaxf(flow, 0.0f);
            out[row[j]] = flow;
        }
    }
}

extern "C" void kernel_launch(void* const* d_in, const int* in_sizes, int n_in,
                              void* d_out, int out_size)
{
    const float* x  = (const float*)d_in[0];   // [N,4]
    const float* S1 = (const float*)d_in[1];   // [N,1]
    const float* W1 = (const float*)d_in[2];   // [3,4,6]
    const float* b1 = (const float*)d_in[3];   // [3,6]
    const float* W2 = (const float*)d_in[4];   // [3,6,6]
    const float* b2 = (const float*)d_in[5];   // [3,6]
    const float* W3 = (const float*)d_in[6];   // [3,6,1]
    const float* b3 = (const float*)d_in[7];   // [3,1]
    float* out = (float*)d_out;

    const int n = in_sizes[1];                 // S1 has N elements
    const int threads_needed = (n + RPT - 1) / RPT;
    const int blocks = (threads_needed + TPB - 1) / TPB;
    const int gstride = blocks * TPB;

    subsurface_flow_kernel<<<blocks, TPB>>>(
        (const float4*)x, S1, W1, b1, W2, b2, W3, b3, out, n, gstride);
}